// round 2
// baseline (speedup 1.0000x reference)
#include <cuda_runtime.h>
#include <math.h>

// Problem constants
#define BB   2
#define LL   2048
#define DD   1024
#define HH   16
#define DKK  64
#define UU   40
#define BHN  (BB*HH)

// Scratch (static __device__ arrays per harness rules; no cudaMalloc anywhere)
__device__ float g_Q[(size_t)BHN*LL*DKK];   // [B,H,L,DK] 16 MB
__device__ float g_K[(size_t)BHN*LL*DKK];   // 16 MB
__device__ float g_V[(size_t)BHN*LL*DKK];   // 16 MB
__device__ float g_M[(size_t)BHN*LL];       // sparsity measure
__device__ int   g_top[BHN*UU];             // top-k indices
__device__ float g_probs_scratch[(size_t)BHN*UU*LL]; // fallback if out only holds attn

// ---------------------------------------------------------------------------
// Kernel 1: projection GEMM  out = X @ W^T + b, written directly in
// [B,H,L,DK] head-split layout.  64x64 tile, 16x16 threads, 4x4 per thread.
// which: 0 -> g_Q, 1 -> g_K, 2 -> g_V
// ---------------------------------------------------------------------------
__global__ void proj_gemm(const float* __restrict__ X, const float* __restrict__ W,
                          const float* __restrict__ bias, int which)
{
    __shared__ float As[16][64+1];
    __shared__ float Bs[16][64+1];
    float* __restrict__ out = (which == 0) ? g_Q : (which == 1) ? g_K : g_V;

    const int tx = threadIdx.x, ty = threadIdx.y;
    const int tid = ty*16 + tx;
    const int rowBase = blockIdx.y * 64;   // over B*L = 4096
    const int colBase = blockIdx.x * 64;   // over D = 1024

    float acc[4][4];
#pragma unroll
    for (int i = 0; i < 4; i++)
#pragma unroll
        for (int j = 0; j < 4; j++) acc[i][j] = 0.0f;

    const int m  = tid >> 2;        // 0..63
    const int kq = (tid & 3) * 4;   // 0,4,8,12

    for (int k0 = 0; k0 < DD; k0 += 16) {
        float4 v = *(const float4*)(X + (size_t)(rowBase + m)*DD + k0 + kq);
        As[kq+0][m] = v.x; As[kq+1][m] = v.y; As[kq+2][m] = v.z; As[kq+3][m] = v.w;
        float4 w = *(const float4*)(W + (size_t)(colBase + m)*DD + k0 + kq);
        Bs[kq+0][m] = w.x; Bs[kq+1][m] = w.y; Bs[kq+2][m] = w.z; Bs[kq+3][m] = w.w;
        __syncthreads();
#pragma unroll
        for (int kk = 0; kk < 16; kk++) {
            float a[4], b[4];
#pragma unroll
            for (int i = 0; i < 4; i++) a[i] = As[kk][ty*4 + i];
#pragma unroll
            for (int j = 0; j < 4; j++) b[j] = Bs[kk][tx*4 + j];
#pragma unroll
            for (int i = 0; i < 4; i++)
#pragma unroll
                for (int j = 0; j < 4; j++) acc[i][j] = fmaf(a[i], b[j], acc[i][j]);
        }
        __syncthreads();
    }

#pragma unroll
    for (int i = 0; i < 4; i++) {
        const int r  = rowBase + ty*4 + i;
        const int bb = r / LL;
        const int l  = r % LL;
#pragma unroll
        for (int j = 0; j < 4; j++) {
            const int c = colBase + tx*4 + j;
            const int h = c >> 6;          // c / DK
            const int d = c & (DKK - 1);
            out[(((size_t)(bb*HH + h))*LL + l)*DKK + d] = acc[i][j] + bias[c];
        }
    }
}

// ---------------------------------------------------------------------------
// Kernel 2: fused scores + M.  For each (b,h) and 64-row query tile, stream
// K in 64-row tiles, compute 64x64 score tiles, keep running rowmax/rowsum.
// M = max - sum/L. Never materializes the LxL score matrix.
// ---------------------------------------------------------------------------
__global__ void scores_m_kernel()
{
    const int bh    = blockIdx.y;
    const int qBase = blockIdx.x * 64;
    const float* __restrict__ Qb = g_Q + (size_t)bh*LL*DKK;
    const float* __restrict__ Kb = g_K + (size_t)bh*LL*DKK;

    __shared__ float Qs[64][65];
    __shared__ float Ks[64][65];
    __shared__ float red[16][4][17];

    const int tx = threadIdx.x, ty = threadIdx.y;
    const int tid = ty*16 + tx;

    // load Q tile (64 rows x 64 dk), transposed as [d][row]
#pragma unroll
    for (int p = 0; p < 4; p++) {
        const int i4  = tid + p*256;
        const int row = i4 >> 4;
        const int dq  = (i4 & 15) * 4;
        float4 v = *(const float4*)(Qb + (size_t)(qBase + row)*DKK + dq);
        Qs[dq+0][row] = v.x; Qs[dq+1][row] = v.y; Qs[dq+2][row] = v.z; Qs[dq+3][row] = v.w;
    }

    float thrMax[4], thrSum[4];
#pragma unroll
    for (int i = 0; i < 4; i++) { thrMax[i] = -INFINITY; thrSum[i] = 0.0f; }

    for (int kt = 0; kt < LL; kt += 64) {
        __syncthreads();   // protect Ks reuse (and first-iter Qs fill)
#pragma unroll
        for (int p = 0; p < 4; p++) {
            const int i4  = tid + p*256;
            const int row = i4 >> 4;
            const int dq  = (i4 & 15) * 4;
            float4 v = *(const float4*)(Kb + (size_t)(kt + row)*DKK + dq);
            Ks[dq+0][row] = v.x; Ks[dq+1][row] = v.y; Ks[dq+2][row] = v.z; Ks[dq+3][row] = v.w;
        }
        __syncthreads();

        float acc[4][4];
#pragma unroll
        for (int i = 0; i < 4; i++)
#pragma unroll
            for (int j = 0; j < 4; j++) acc[i][j] = 0.0f;

#pragma unroll 16
        for (int d = 0; d < 64; d++) {
            float a[4], b[4];
#pragma unroll
            for (int i = 0; i < 4; i++) a[i] = Qs[d][ty*4 + i];
#pragma unroll
            for (int j = 0; j < 4; j++) b[j] = Ks[d][tx*4 + j];
#pragma unroll
            for (int i = 0; i < 4; i++)
#pragma unroll
                for (int j = 0; j < 4; j++) acc[i][j] = fmaf(a[i], b[j], acc[i][j]);
        }
#pragma unroll
        for (int i = 0; i < 4; i++)
#pragma unroll
            for (int j = 0; j < 4; j++) {
                thrMax[i] = fmaxf(thrMax[i], acc[i][j]);
                thrSum[i] += acc[i][j];
            }
    }

    __syncthreads();
#pragma unroll
    for (int i = 0; i < 4; i++) red[ty][i][tx] = thrMax[i];
    __syncthreads();
    float rowmax[4];
    if (tx == 0) {
#pragma unroll
        for (int i = 0; i < 4; i++) {
            float mv = -INFINITY;
            for (int t = 0; t < 16; t++) mv = fmaxf(mv, red[ty][i][t]);
            rowmax[i] = mv;
        }
    }
    __syncthreads();
#pragma unroll
    for (int i = 0; i < 4; i++) red[ty][i][tx] = thrSum[i];
    __syncthreads();
    if (tx == 0) {
#pragma unroll
        for (int i = 0; i < 4; i++) {
            float s = 0.0f;
            for (int t = 0; t < 16; t++) s += red[ty][i][t];
            g_M[(size_t)bh*LL + qBase + ty*4 + i] = rowmax[i] - s * (1.0f / LL);
        }
    }
}

// ---------------------------------------------------------------------------
// Kernel 3: top-U of M per (b,h), jax.lax.top_k order (desc value, tie ->
// lower index). Iterative argmax, 40 passes.
// ---------------------------------------------------------------------------
__global__ void topk_kernel()
{
    const int bh  = blockIdx.x;
    const int tid = threadIdx.x;
    __shared__ float vals[LL];
    __shared__ float rv[256];
    __shared__ int   ri[256];

    for (int i = tid; i < LL; i += 256) vals[i] = g_M[(size_t)bh*LL + i];
    __syncthreads();

    for (int it = 0; it < UU; it++) {
        float bv = -INFINITY; int bi = LL;
        for (int i = tid; i < LL; i += 256) {
            float v = vals[i];
            if (v > bv || (v == bv && i < bi)) { bv = v; bi = i; }
        }
        rv[tid] = bv; ri[tid] = bi;
        __syncthreads();
        for (int s = 128; s > 0; s >>= 1) {
            if (tid < s) {
                float v2 = rv[tid + s]; int i2 = ri[tid + s];
                if (v2 > rv[tid] || (v2 == rv[tid] && i2 < ri[tid])) { rv[tid] = v2; ri[tid] = i2; }
            }
            __syncthreads();
        }
        if (tid == 0) { g_top[bh*UU + it] = ri[0]; vals[ri[0]] = -INFINITY; }
        __syncthreads();
    }
}

// ---------------------------------------------------------------------------
// Kernel 4: one block per (b,h,u): scores row vs all K, causal additive mask
// (score - 1e9 for l > qi), softmax, write probs, then attn = probs @ V.
// ---------------------------------------------------------------------------
__global__ void attn_kernel(float* __restrict__ outAttn, float* __restrict__ outProbs)
{
    const int u = blockIdx.x, h = blockIdx.y, b = blockIdx.z;
    const int bh = b*HH + h;
    const int tid = threadIdx.x;
    const int qi = g_top[bh*UU + u];

    __shared__ float qrow[DKK];
    __shared__ float sc[LL];
    __shared__ float red[256];
    __shared__ float pr[4][64];

    const float* __restrict__ Kb = g_K + (size_t)bh*LL*DKK;
    const float* __restrict__ Vb = g_V + (size_t)bh*LL*DKK;

    if (tid < DKK) qrow[tid] = g_Q[((size_t)bh*LL + qi)*DKK + tid];
    __syncthreads();

    const float scale = 0.125f;  // 1/sqrt(64)
    for (int l = tid; l < LL; l += 256) {
        const float4* kp = (const float4*)(Kb + (size_t)l*DKK);
        float acc = 0.0f;
#pragma unroll
        for (int d4 = 0; d4 < 16; d4++) {
            float4 kv = kp[d4];
            acc = fmaf(qrow[d4*4+0], kv.x, acc);
            acc = fmaf(qrow[d4*4+1], kv.y, acc);
            acc = fmaf(qrow[d4*4+2], kv.z, acc);
            acc = fmaf(qrow[d4*4+3], kv.w, acc);
        }
        float s = acc * scale;
        if (l > qi) s -= 1e9f;   // additive mask, matches reference
        sc[l] = s;
    }
    __syncthreads();

    // rowmax
    float lm = -INFINITY;
    for (int l = tid; l < LL; l += 256) lm = fmaxf(lm, sc[l]);
    red[tid] = lm; __syncthreads();
    for (int s = 128; s > 0; s >>= 1) { if (tid < s) red[tid] = fmaxf(red[tid], red[tid+s]); __syncthreads(); }
    const float mx = red[0];
    __syncthreads();

    // exp + sum
    float ls = 0.0f;
    for (int l = tid; l < LL; l += 256) { float e = expf(sc[l] - mx); sc[l] = e; ls += e; }
    red[tid] = ls; __syncthreads();
    for (int s = 128; s > 0; s >>= 1) { if (tid < s) red[tid] += red[tid+s]; __syncthreads(); }
    const float inv = 1.0f / red[0];

    // write probs [B,H,U,L]
    float* pOut = outProbs + ((size_t)bh*UU + u)*LL;
    for (int l = tid; l < LL; l += 256) pOut[l] = sc[l] * inv;

    // attn = probs @ V  -> out[b, u, h*DK + d]
    const int d = tid & 63, g = tid >> 6;
    float part = 0.0f;
    const int l0 = g * (LL/4), l1 = l0 + (LL/4);
    for (int l = l0; l < l1; l++) part = fmaf(sc[l], Vb[(size_t)l*DKK + d], part);
    pr[g][d] = part;
    __syncthreads();
    if (g == 0) {
        float tot = (pr[0][d] + pr[1][d] + pr[2][d] + pr[3][d]) * inv;
        outAttn[((size_t)b*UU + u)*DD + h*DKK + d] = tot;
    }
}

// ---------------------------------------------------------------------------
extern "C" void kernel_launch(void* const* d_in, const int* in_sizes, int n_in,
                              void* d_out, int out_size)
{
    const float* query = (const float*)d_in[0];
    const float* key   = (const float*)d_in[1];
    const float* value = (const float*)d_in[2];
    const float* Wq    = (const float*)d_in[3];
    const float* bq    = (const float*)d_in[4];
    const float* Wk    = (const float*)d_in[5];
    const float* bk    = (const float*)d_in[6];
    const float* Wv    = (const float*)d_in[7];
    const float* bv    = (const float*)d_in[8];
    float* out = (float*)d_out;

    const size_t attnN  = (size_t)BB*UU*DD;      // 81920
    const size_t probsN = (size_t)BHN*UU*LL;     // 2621440

    float* probsOut;
    if ((size_t)out_size >= attnN + probsN) {
        probsOut = out + attnN;
    } else {
        void* p = nullptr;
        cudaGetSymbolAddress(&p, g_probs_scratch);  // host query, capture-safe
        probsOut = (float*)p;
    }

    dim3 pb(16, 16);
    dim3 pg(DD/64, (BB*LL)/64);                  // (16, 64)
    proj_gemm<<<pg, pb>>>(query, Wq, bq, 0);
    proj_gemm<<<pg, pb>>>(key,   Wk, bk, 1);
    proj_gemm<<<pg, pb>>>(value, Wv, bv, 2);

    scores_m_kernel<<<dim3(LL/64, BHN), dim3(16, 16)>>>();
    topk_kernel<<<BHN, 256>>>();
    attn_kernel<<<dim3(UU, HH, BB), 256>>>(out, probsOut);
}

// round 3
// speedup vs baseline: 2.2095x; 2.2095x over previous
#include <cuda_runtime.h>
#include <math.h>

// Problem constants
#define BB   2
#define LL   2048
#define DD   1024
#define HH   16
#define DKK  64
#define UU   40
#define BHN  (BB*HH)

#define PAD  132   // shared stride in floats: multiple of 4 (keeps float4 alignment), not mult of 32 banks

// Scratch (static __device__ arrays; no cudaMalloc anywhere)
__device__ float g_Q[(size_t)BHN*LL*DKK];   // [B,H,L,DK]
__device__ float g_K[(size_t)BHN*LL*DKK];
__device__ float g_V[(size_t)BHN*LL*DKK];
__device__ float g_M[(size_t)BHN*LL];
__device__ int   g_top[BHN*UU];
__device__ float g_probs_scratch[(size_t)BHN*UU*LL];

// ---------------------------------------------------------------------------
// Kernel 1: projection GEMM  out = X @ W^T + b  -> [B,H,L,DK] layout.
// 128x128 tile, 256 threads, 8x8 per thread (4+64 split columns/rows),
// K-chunk = 16, LDS.128 operand loads.
// blockIdx.z selects Q/K/V.
// ---------------------------------------------------------------------------
__global__ void __launch_bounds__(256)
proj_gemm128(const float* __restrict__ Xq, const float* __restrict__ Xk, const float* __restrict__ Xv,
             const float* __restrict__ Wqp, const float* __restrict__ Wkp, const float* __restrict__ Wvp,
             const float* __restrict__ bqp, const float* __restrict__ bkp, const float* __restrict__ bvp)
{
    const int which = blockIdx.z;
    const float* __restrict__ X    = (which == 0) ? Xq  : (which == 1) ? Xk  : Xv;
    const float* __restrict__ W    = (which == 0) ? Wqp : (which == 1) ? Wkp : Wvp;
    const float* __restrict__ bias = (which == 0) ? bqp : (which == 1) ? bkp : bvp;
    float* __restrict__ out        = (which == 0) ? g_Q : (which == 1) ? g_K : g_V;

    __shared__ float As[16][PAD];   // As[k][m]  (X rows transposed)
    __shared__ float Bs[16][PAD];   // Bs[k][n]  (W rows transposed)

    const int tx = threadIdx.x, ty = threadIdx.y;
    const int tid = ty*16 + tx;
    const int rowBase = blockIdx.y * 128;   // over B*L = 4096
    const int colBase = blockIdx.x * 128;   // over D = 1024

    float acc[8][8];
#pragma unroll
    for (int i = 0; i < 8; i++)
#pragma unroll
        for (int j = 0; j < 8; j++) acc[i][j] = 0.0f;

    // load assignment: 512 float4 per matrix per chunk -> 2 per thread
    const int f0_row = (tid       ) >> 2, f0_kq = ((tid       ) & 3) * 4;
    const int f1_row = (tid + 256 ) >> 2, f1_kq = ((tid + 256 ) & 3) * 4;

    for (int k0 = 0; k0 < DD; k0 += 16) {
        {
            float4 v = *(const float4*)(X + (size_t)(rowBase + f0_row)*DD + k0 + f0_kq);
            As[f0_kq+0][f0_row] = v.x; As[f0_kq+1][f0_row] = v.y;
            As[f0_kq+2][f0_row] = v.z; As[f0_kq+3][f0_row] = v.w;
            v = *(const float4*)(X + (size_t)(rowBase + f1_row)*DD + k0 + f1_kq);
            As[f1_kq+0][f1_row] = v.x; As[f1_kq+1][f1_row] = v.y;
            As[f1_kq+2][f1_row] = v.z; As[f1_kq+3][f1_row] = v.w;
            v = *(const float4*)(W + (size_t)(colBase + f0_row)*DD + k0 + f0_kq);
            Bs[f0_kq+0][f0_row] = v.x; Bs[f0_kq+1][f0_row] = v.y;
            Bs[f0_kq+2][f0_row] = v.z; Bs[f0_kq+3][f0_row] = v.w;
            v = *(const float4*)(W + (size_t)(colBase + f1_row)*DD + k0 + f1_kq);
            Bs[f1_kq+0][f1_row] = v.x; Bs[f1_kq+1][f1_row] = v.y;
            Bs[f1_kq+2][f1_row] = v.z; Bs[f1_kq+3][f1_row] = v.w;
        }
        __syncthreads();
#pragma unroll
        for (int kk = 0; kk < 16; kk++) {
            float4 a0 = *(const float4*)&As[kk][ty*4];
            float4 a1 = *(const float4*)&As[kk][64 + ty*4];
            float4 b0 = *(const float4*)&Bs[kk][tx*4];
            float4 b1 = *(const float4*)&Bs[kk][64 + tx*4];
            float a[8] = {a0.x,a0.y,a0.z,a0.w, a1.x,a1.y,a1.z,a1.w};
            float b[8] = {b0.x,b0.y,b0.z,b0.w, b1.x,b1.y,b1.z,b1.w};
#pragma unroll
            for (int i = 0; i < 8; i++)
#pragma unroll
                for (int j = 0; j < 8; j++) acc[i][j] = fmaf(a[i], b[j], acc[i][j]);
        }
        __syncthreads();
    }

#pragma unroll
    for (int i = 0; i < 8; i++) {
        const int rloc = (i < 4) ? (ty*4 + i) : (64 + ty*4 + i - 4);
        const int r  = rowBase + rloc;
        const int bb = r >> 11;            // / LL
        const int l  = r & (LL - 1);
#pragma unroll
        for (int j = 0; j < 8; j++) {
            const int cloc = (j < 4) ? (tx*4 + j) : (64 + tx*4 + j - 4);
            const int c = colBase + cloc;
            const int h = c >> 6;
            const int d = c & (DKK - 1);
            out[(((size_t)(bb*HH + h))*LL + l)*DKK + d] = acc[i][j] + bias[c];
        }
    }
}

// ---------------------------------------------------------------------------
// Kernel 2: fused scores + M.  Block covers 128 query rows x ALL 2048 keys
// for one (b,h): outer loop over 16 K tiles of 128, inner loop over 4
// dk-chunks of 16.  Same 8x8 micro-tile / LDS.128 scheme. Running max/sum
// per row, reduced across tx at the end.  M = max - sum/L.
// ---------------------------------------------------------------------------
__global__ void __launch_bounds__(256) scores_m_kernel()
{
    const int bh    = blockIdx.y;
    const int qBase = blockIdx.x * 128;
    const float* __restrict__ Qb = g_Q + (size_t)bh*LL*DKK;
    const float* __restrict__ Kb = g_K + (size_t)bh*LL*DKK;

    __shared__ float As[16][PAD];    // Q chunk transposed [d][qrow]
    __shared__ float Bs[16][PAD];    // K chunk transposed [d][krow]
    __shared__ float red[128][17];

    const int tx = threadIdx.x, ty = threadIdx.y;
    const int tid = ty*16 + tx;

    const int f0_row = (tid      ) >> 2, f0_kq = ((tid      ) & 3) * 4;
    const int f1_row = (tid + 256) >> 2, f1_kq = ((tid + 256) & 3) * 4;

    float thrMax[8], thrSum[8];
#pragma unroll
    for (int i = 0; i < 8; i++) { thrMax[i] = -INFINITY; thrSum[i] = 0.0f; }

    for (int kt = 0; kt < LL; kt += 128) {
        float acc[8][8];
#pragma unroll
        for (int i = 0; i < 8; i++)
#pragma unroll
            for (int j = 0; j < 8; j++) acc[i][j] = 0.0f;

        for (int d0 = 0; d0 < DKK; d0 += 16) {
            __syncthreads();   // protect previous-chunk reads
            {
                float4 v = *(const float4*)(Qb + (size_t)(qBase + f0_row)*DKK + d0 + f0_kq);
                As[f0_kq+0][f0_row] = v.x; As[f0_kq+1][f0_row] = v.y;
                As[f0_kq+2][f0_row] = v.z; As[f0_kq+3][f0_row] = v.w;
                v = *(const float4*)(Qb + (size_t)(qBase + f1_row)*DKK + d0 + f1_kq);
                As[f1_kq+0][f1_row] = v.x; As[f1_kq+1][f1_row] = v.y;
                As[f1_kq+2][f1_row] = v.z; As[f1_kq+3][f1_row] = v.w;
                v = *(const float4*)(Kb + (size_t)(kt + f0_row)*DKK + d0 + f0_kq);
                Bs[f0_kq+0][f0_row] = v.x; Bs[f0_kq+1][f0_row] = v.y;
                Bs[f0_kq+2][f0_row] = v.z; Bs[f0_kq+3][f0_row] = v.w;
                v = *(const float4*)(Kb + (size_t)(kt + f1_row)*DKK + d0 + f1_kq);
                Bs[f1_kq+0][f1_row] = v.x; Bs[f1_kq+1][f1_row] = v.y;
                Bs[f1_kq+2][f1_row] = v.z; Bs[f1_kq+3][f1_row] = v.w;
            }
            __syncthreads();
#pragma unroll
            for (int kk = 0; kk < 16; kk++) {
                float4 a0 = *(const float4*)&As[kk][ty*4];
                float4 a1 = *(const float4*)&As[kk][64 + ty*4];
                float4 b0 = *(const float4*)&Bs[kk][tx*4];
                float4 b1 = *(const float4*)&Bs[kk][64 + tx*4];
                float a[8] = {a0.x,a0.y,a0.z,a0.w, a1.x,a1.y,a1.z,a1.w};
                float b[8] = {b0.x,b0.y,b0.z,b0.w, b1.x,b1.y,b1.z,b1.w};
#pragma unroll
                for (int i = 0; i < 8; i++)
#pragma unroll
                    for (int j = 0; j < 8; j++) acc[i][j] = fmaf(a[i], b[j], acc[i][j]);
            }
        }

#pragma unroll
        for (int i = 0; i < 8; i++)
#pragma unroll
            for (int j = 0; j < 8; j++) {
                thrMax[i] = fmaxf(thrMax[i], acc[i][j]);
                thrSum[i] += acc[i][j];
            }
    }

    // reduce across tx (16 threads cover the 128 columns of each row slice)
    __syncthreads();
#pragma unroll
    for (int i = 0; i < 8; i++) {
        const int rloc = (i < 4) ? (ty*4 + i) : (64 + ty*4 + i - 4);
        red[rloc][tx] = thrMax[i];
    }
    __syncthreads();
    float mv = -INFINITY;
    if (tid < 128) {
#pragma unroll
        for (int t = 0; t < 16; t++) mv = fmaxf(mv, red[tid][t]);
    }
    __syncthreads();
#pragma unroll
    for (int i = 0; i < 8; i++) {
        const int rloc = (i < 4) ? (ty*4 + i) : (64 + ty*4 + i - 4);
        red[rloc][tx] = thrSum[i];
    }
    __syncthreads();
    if (tid < 128) {
        float s = 0.0f;
#pragma unroll
        for (int t = 0; t < 16; t++) s += red[tid][t];
        g_M[(size_t)bh*LL + qBase + tid] = mv - s * (1.0f / LL);
    }
}

// ---------------------------------------------------------------------------
// Kernel 3: top-U of M per (b,h), jax.lax.top_k order (desc value, tie ->
// lower index). Iterative argmax, 40 passes.
// ---------------------------------------------------------------------------
__global__ void topk_kernel()
{
    const int bh  = blockIdx.x;
    const int tid = threadIdx.x;
    __shared__ float vals[LL];
    __shared__ float rv[256];
    __shared__ int   ri[256];

    for (int i = tid; i < LL; i += 256) vals[i] = g_M[(size_t)bh*LL + i];
    __syncthreads();

    for (int it = 0; it < UU; it++) {
        float bv = -INFINITY; int bi = LL;
        for (int i = tid; i < LL; i += 256) {
            float v = vals[i];
            if (v > bv || (v == bv && i < bi)) { bv = v; bi = i; }
        }
        rv[tid] = bv; ri[tid] = bi;
        __syncthreads();
        for (int s = 128; s > 0; s >>= 1) {
            if (tid < s) {
                float v2 = rv[tid + s]; int i2 = ri[tid + s];
                if (v2 > rv[tid] || (v2 == rv[tid] && i2 < ri[tid])) { rv[tid] = v2; ri[tid] = i2; }
            }
            __syncthreads();
        }
        if (tid == 0) { g_top[bh*UU + it] = ri[0]; vals[ri[0]] = -INFINITY; }
        __syncthreads();
    }
}

// ---------------------------------------------------------------------------
// Kernel 4: one block per (b,h,u): scores vs all K, causal additive mask,
// softmax, probs out, attn = probs @ V.
// ---------------------------------------------------------------------------
__global__ void attn_kernel(float* __restrict__ outAttn, float* __restrict__ outProbs)
{
    const int u = blockIdx.x, h = blockIdx.y, b = blockIdx.z;
    const int bh = b*HH + h;
    const int tid = threadIdx.x;
    const int qi = g_top[bh*UU + u];

    __shared__ float qrow[DKK];
    __shared__ float sc[LL];
    __shared__ float red[256];
    __shared__ float pr[4][64];

    const float* __restrict__ Kb = g_K + (size_t)bh*LL*DKK;
    const float* __restrict__ Vb = g_V + (size_t)bh*LL*DKK;

    if (tid < DKK) qrow[tid] = g_Q[((size_t)bh*LL + qi)*DKK + tid];
    __syncthreads();

    const float scale = 0.125f;  // 1/sqrt(64)
    for (int l = tid; l < LL; l += 256) {
        const float4* kp = (const float4*)(Kb + (size_t)l*DKK);
        float acc = 0.0f;
#pragma unroll
        for (int d4 = 0; d4 < 16; d4++) {
            float4 kv = kp[d4];
            acc = fmaf(qrow[d4*4+0], kv.x, acc);
            acc = fmaf(qrow[d4*4+1], kv.y, acc);
            acc = fmaf(qrow[d4*4+2], kv.z, acc);
            acc = fmaf(qrow[d4*4+3], kv.w, acc);
        }
        float s = acc * scale;
        if (l > qi) s -= 1e9f;
        sc[l] = s;
    }
    __syncthreads();

    float lm = -INFINITY;
    for (int l = tid; l < LL; l += 256) lm = fmaxf(lm, sc[l]);
    red[tid] = lm; __syncthreads();
    for (int s = 128; s > 0; s >>= 1) { if (tid < s) red[tid] = fmaxf(red[tid], red[tid+s]); __syncthreads(); }
    const float mx = red[0];
    __syncthreads();

    float ls = 0.0f;
    for (int l = tid; l < LL; l += 256) { float e = expf(sc[l] - mx); sc[l] = e; ls += e; }
    red[tid] = ls; __syncthreads();
    for (int s = 128; s > 0; s >>= 1) { if (tid < s) red[tid] += red[tid+s]; __syncthreads(); }
    const float inv = 1.0f / red[0];

    float* pOut = outProbs + ((size_t)bh*UU + u)*LL;
    for (int l = tid; l < LL; l += 256) pOut[l] = sc[l] * inv;

    const int d = tid & 63, g = tid >> 6;
    float part = 0.0f;
    const int l0 = g * (LL/4), l1 = l0 + (LL/4);
    for (int l = l0; l < l1; l++) part = fmaf(sc[l], Vb[(size_t)l*DKK + d], part);
    pr[g][d] = part;
    __syncthreads();
    if (g == 0) {
        float tot = (pr[0][d] + pr[1][d] + pr[2][d] + pr[3][d]) * inv;
        outAttn[((size_t)b*UU + u)*DD + h*DKK + d] = tot;
    }
}

// ---------------------------------------------------------------------------
extern "C" void kernel_launch(void* const* d_in, const int* in_sizes, int n_in,
                              void* d_out, int out_size)
{
    const float* query = (const float*)d_in[0];
    const float* key   = (const float*)d_in[1];
    const float* value = (const float*)d_in[2];
    const float* Wq    = (const float*)d_in[3];
    const float* bq    = (const float*)d_in[4];
    const float* Wk    = (const float*)d_in[5];
    const float* bk    = (const float*)d_in[6];
    const float* Wv    = (const float*)d_in[7];
    const float* bv    = (const float*)d_in[8];
    float* out = (float*)d_out;

    const size_t attnN  = (size_t)BB*UU*DD;      // 81920
    const size_t probsN = (size_t)BHN*UU*LL;     // 2621440

    float* probsOut;
    if ((size_t)out_size >= attnN + probsN) {
        probsOut = out + attnN;
    } else {
        void* p = nullptr;
        cudaGetSymbolAddress(&p, g_probs_scratch);
        probsOut = (float*)p;
    }

    dim3 pb(16, 16);
    dim3 pg(DD/128, (BB*LL)/128, 3);             // (8, 32, 3)
    proj_gemm128<<<pg, pb>>>(query, key, value, Wq, Wk, Wv, bq, bk, bv);

    scores_m_kernel<<<dim3(LL/128, BHN), dim3(16, 16)>>>();
    topk_kernel<<<BHN, 256>>>();
    attn_kernel<<<dim3(UU, HH, BB), 256>>>(out, probsOut);
}